// round 15
// baseline (speedup 1.0000x reference)
#include <cuda_runtime.h>
#include <stdint.h>

#define BATCH    16
#define NBOX     4096
#define NCLS     80
#define MAX_DET  100
#define IOU_THR  0.5f
#define CONF_THR 0.5f
#define FULL     0xffffffffu
#define CHUNK    256
#define SUBS     4                  // candidate sub-threads in A1/A2
#define NW       (CHUNK / 32)       // 8 mask words
#define THREADS  1024

// scratch: per-row sort keys  (score_bits << 32) | (0xFFFFFFFF - idx)
__device__ unsigned long long g_keys[BATCH * NBOX];

// guarded IoU>0.5 test. Fast path: IoU>0.5 <=> 3*inter > aa+ab.
// g>0 implies inter>0 (areas >= 0), so no separate inter>0 test needed.
// Borderline band falls back to the exact divide with
// uni = fl(fl(aa+ab) - inter), identical rounding to the reference.
__device__ __forceinline__ bool iou_gt(float y1a, float x1a, float y2a, float x2a, float aa,
                                       float y1b, float x1b, float y2b, float x2b, float ab)
{
    float ih = fmaxf(0.0f, fminf(y2a, y2b) - fmaxf(y1a, y1b));
    float iw = fmaxf(0.0f, fminf(x2a, x2b) - fmaxf(x1a, x1b));
    float inter = ih * iw;
    float t   = aa + ab;
    float uni = t - inter;
    float g   = fmaf(3.0f, inter, -t);           // = 2*(inter - 0.5*uni)
    if (fabsf(g) <= uni * 1e-5f) {               // borderline: exact semantics
        float iou = (inter > 0.0f) ? inter / uni : 0.0f;
        return iou > IOU_THR;
    }
    return g > 0.0f;
}

__device__ __forceinline__ void ce64(unsigned long long& a, unsigned long long& b, bool desc)
{
    bool sw = desc ? (a < b) : (a > b);
    if (sw) { unsigned long long t = a; a = b; b = t; }
}

__device__ __forceinline__ unsigned long long shfl_step(unsigned long long v, int j,
                                                        bool desc, int lane)
{
    unsigned long long w = __shfl_xor_sync(FULL, v, j);
    bool upper   = (lane & j) != 0;
    bool takeMax = desc ^ upper;
    return takeMax ? (v > w ? v : w) : (v < w ? v : w);
}

// ---------------------------------------------------------------------------
// Kernel 1: softmax(square(x*10)) per row, write cls_predictions, emit keys.
// ---------------------------------------------------------------------------
__global__ void __launch_bounds__(256)
softmax_key_kernel(const float* __restrict__ cls_in,
                   float* __restrict__ cls_out,
                   unsigned long long* __restrict__ keys)
{
    const int lane = threadIdx.x & 31;
    const int row  = blockIdx.x * (blockDim.x >> 5) + (threadIdx.x >> 5);
    if (row >= BATCH * NBOX) return;

    const float* in = cls_in + (size_t)row * NCLS;

    const bool has2 = lane < (NCLS - 64);
    float x0 = in[lane]      * 10.0f;
    float x1 = in[lane + 32] * 10.0f;
    float x2 = has2 ? in[lane + 64] * 10.0f : 0.0f;
    float a0 = x0 * x0, a1 = x1 * x1, a2 = x2 * x2;

    float amax = fmaxf(a0, a1);
    if (has2) amax = fmaxf(amax, a2);
    amax = __uint_as_float(__reduce_max_sync(FULL, __float_as_uint(amax)));

    float e0 = expf(a0 - amax);
    float e1 = expf(a1 - amax);
    float e2 = has2 ? expf(a2 - amax) : 0.0f;

    float s = e0 + e1 + e2;
    #pragma unroll
    for (int o = 16; o; o >>= 1)
        s += __shfl_xor_sync(FULL, s, o);

    const float recip = 1.0f / s;

    float* out = cls_out + (size_t)row * NCLS;
    out[lane]      = e0 * recip;
    out[lane + 32] = e1 * recip;
    if (has2) out[lane + 64] = e2 * recip;

    if (lane == 0) {
        const unsigned n = (unsigned)(row & (NBOX - 1));
        keys[row] = ((unsigned long long)__float_as_uint(recip) << 32)
                  | (unsigned long long)(0xffffffffu - n);
    }
}

// ---------------------------------------------------------------------------
// Kernel 1.5a: presort — sort each 1024-run (global stages k=2..1024).
// ---------------------------------------------------------------------------
__global__ void __launch_bounds__(512)
presort_kernel(unsigned long long* __restrict__ keys)
{
    __shared__ unsigned long long s[1024];
    const int tid  = threadIdx.x;
    const int lane = tid & 31;
    const bool desc_run = ((blockIdx.x & 1) == 0);
    unsigned long long* kg = keys + (size_t)blockIdx.x * 1024;

    s[tid]       = kg[tid];
    s[tid + 512] = kg[tid + 512];
    __syncthreads();

    {
        const int i0 = tid, i1 = tid + 512;
        unsigned long long v0 = s[i0], v1 = s[i1];
        #pragma unroll
        for (int k = 2; k <= 32; k <<= 1) {
            const bool d0 = ((i0 & k) == 0);
            #pragma unroll
            for (int j = k >> 1; j >= 1; j >>= 1) {
                v0 = shfl_step(v0, j, d0, lane);
                v1 = shfl_step(v1, j, d0, lane);
            }
        }
        s[i0] = v0; s[i1] = v1;
    }
    __syncthreads();

    for (int k = 64; k <= 1024; k <<= 1) {
        for (int j = k >> 1; j >= 32; j >>= 1) {
            const int p = tid;
            const int i = ((p & ~(j - 1)) << 1) | (p & (j - 1));
            const int l = i | j;
            const bool d = (k == 1024) ? desc_run : ((i & k) == 0);
            unsigned long long a = s[i], c = s[l];
            bool sw = d ? (a < c) : (a > c);
            if (sw) { s[i] = c; s[l] = a; }
            __syncthreads();
        }
        {
            const int i0 = tid, i1 = tid + 512;
            unsigned long long v0 = s[i0], v1 = s[i1];
            const bool d0 = (k == 1024) ? desc_run : ((i0 & k) == 0);
            const bool d1 = (k == 1024) ? desc_run : ((i1 & k) == 0);
            #pragma unroll
            for (int j = 16; j >= 1; j >>= 1) {
                v0 = shfl_step(v0, j, d0, lane);
                v1 = shfl_step(v1, j, d1, lane);
            }
            s[i0] = v0; s[i1] = v1;
        }
        __syncthreads();
    }

    kg[tid]       = s[tid];
    kg[tid + 512] = s[tid + 512];
}

// ---------------------------------------------------------------------------
// Kernel 1.5b: merge2048 — global bitonic stage k=2048 only.
// ---------------------------------------------------------------------------
__global__ void __launch_bounds__(512)
merge2048_kernel(unsigned long long* __restrict__ keys)
{
    __shared__ unsigned long long s[2048];
    const int tid  = threadIdx.x;
    const int lane = tid & 31;
    const int warp = tid >> 5;
    const bool d = ((blockIdx.x & 1) == 0);
    unsigned long long* kg = keys + (size_t)blockIdx.x * 2048;

    #pragma unroll
    for (int m = 0; m < 4; m++) s[tid + m * 512] = kg[tid + m * 512];
    __syncthreads();

    for (int j = 1024; j >= 128; j >>= 1) {
        #pragma unroll
        for (int q = 0; q < 2; q++) {
            const int p = tid + q * 512;
            const int i = ((p & ~(j - 1)) << 1) | (p & (j - 1));
            const int l = i | j;
            unsigned long long a = s[i], c = s[l];
            bool sw = d ? (a < c) : (a > c);
            if (sw) { s[i] = c; s[l] = a; }
        }
        __syncthreads();
    }

    const int base = warp << 7;
    unsigned long long r0 = s[base + lane];
    unsigned long long r1 = s[base + 32 + lane];
    unsigned long long r2 = s[base + 64 + lane];
    unsigned long long r3 = s[base + 96 + lane];
    ce64(r0, r2, d); ce64(r1, r3, d);
    ce64(r0, r1, d); ce64(r2, r3, d);
    #pragma unroll
    for (int j = 16; j >= 1; j >>= 1) {
        r0 = shfl_step(r0, j, d, lane);
        r1 = shfl_step(r1, j, d, lane);
        r2 = shfl_step(r2, j, d, lane);
        r3 = shfl_step(r3, j, d, lane);
    }
    kg[base + lane]      = r0;
    kg[base + 32 + lane] = r1;
    kg[base + 64 + lane] = r2;
    kg[base + 96 + lane] = r3;
}

// ---------------------------------------------------------------------------
// Kernel 2: finish sort (k=4096) + pipelined bitmap NMS.
//   A1 slot : all threads check chunk c vs kept set (with warp early-exit)
//   B slot  : thread 0 resolves chunk c WHILE 992 threads build chunk c+1's
//             suppression matrix and warps 24-31 stage chunk c+2.
// Buffers: chunk staging x3, matrix x2 (disjoint per slot).
// Dynamic smem: float4 sbox[NBOX] | u64 sk[NBOX] | float sarea[NBOX]  (112KB)
// ---------------------------------------------------------------------------
__global__ void __launch_bounds__(THREADS, 1)
nms_kernel(const float* __restrict__ boxes,        // [B,N,4]
           const float* __restrict__ cls_soft,     // [B,N,C]
           const unsigned long long* __restrict__ keys,
           float* __restrict__ nms_box,            // [B,MAX_DET,4]
           float* __restrict__ nms_cls)            // [B,MAX_DET,C]
{
    extern __shared__ char dyn[];
    float4*             sbox  = (float4*)dyn;                       // 64KB
    unsigned long long* sk    = (unsigned long long*)(sbox + NBOX); // 32KB
    float*              sarea = (float*)(sk + NBOX);                // 16KB

    __shared__ float4        kbox[MAX_DET];
    __shared__ float         kar[MAX_DET];
    __shared__ int           kidx[MAX_DET];
    __shared__ float4        cbox[3][CHUNK];       // triple-buffered staging
    __shared__ float         car[3][CHUNK];
    __shared__ int           cidx[3][CHUNK];
    __shared__ unsigned      validw[3][NW];
    __shared__ unsigned char ssup[CHUNK];
    __shared__ __align__(16) unsigned mat32[2][CHUNK][NW];  // 16KB matrices
    __shared__ int s_count, s_stop;

    const int b    = blockIdx.x;
    const int tid  = threadIdx.x;
    const int lane = tid & 31;
    const int warp = tid >> 5;

    // ---- load keys (pre-sorted 2048-runs) + pre-normalized boxes ----
    const float4* bb4 = (const float4*)(boxes + (size_t)b * NBOX * 4);
    #pragma unroll
    for (int s = 0; s < NBOX / THREADS; s++) {
        const int i = tid + s * THREADS;
        sk[i] = keys[b * NBOX + i];
        float4 r = bb4[i];
        float y1 = fminf(r.x, r.z), y2 = fmaxf(r.x, r.z);
        float x1 = fminf(r.y, r.w), x2 = fmaxf(r.y, r.w);
        sbox[i]  = make_float4(y1, x1, y2, x2);
        sarea[i] = (y2 - y1) * (x2 - x1);
    }
    if (tid == 0) { s_count = 0; s_stop = 0; }
    __syncthreads();

    // ---- bitonic stage k=4096 (all descending): smem j=2048..128 ----
    for (int j = 2048; j >= 128; j >>= 1) {
        #pragma unroll
        for (int q = 0; q < NBOX / 2 / THREADS; q++) {
            const int p = tid + q * THREADS;
            const int i = ((p & ~(j - 1)) << 1) | (p & (j - 1));
            const int l = i | j;
            unsigned long long a = sk[i], c = sk[l];
            if (a < c) { sk[i] = c; sk[l] = a; }
        }
        __syncthreads();
    }
    {   // register mega-pass per 128-tile: j = 64, 32, <=16 (desc)
        const int base = warp << 7;
        unsigned long long r0 = sk[base + lane];
        unsigned long long r1 = sk[base + 32 + lane];
        unsigned long long r2 = sk[base + 64 + lane];
        unsigned long long r3 = sk[base + 96 + lane];
        ce64(r0, r2, true); ce64(r1, r3, true);
        ce64(r0, r1, true); ce64(r2, r3, true);
        #pragma unroll
        for (int j = 16; j >= 1; j >>= 1) {
            r0 = shfl_step(r0, j, true, lane);
            r1 = shfl_step(r1, j, true, lane);
            r2 = shfl_step(r2, j, true, lane);
            r3 = shfl_step(r3, j, true, lane);
        }
        sk[base + lane]      = r0;
        sk[base + 32 + lane] = r1;
        sk[base + 64 + lane] = r2;
        sk[base + 96 + lane] = r3;
    }
    __syncthreads();

    // ---- helpers as local lambdas ----
    auto stage = [&](int buf, int base, int c) {   // c in [0,CHUNK), per thread
        const unsigned long long key = sk[base + c];
        const float score = __uint_as_float((unsigned)(key >> 32));
        const int   idx = (int)(0xffffffffu - (unsigned)(key & 0xffffffffu));
        cidx[buf][c] = idx;
        cbox[buf][c] = sbox[idx];
        car[buf][c]  = sarea[idx];
        unsigned vb = __ballot_sync(FULL, score > CONF_THR);
        if ((c & 31) == 0) validw[buf][c >> 5] = vb;
    };
    auto a2_job = [&](int j, int buf, int mb) {    // one (cand,sub) matrix job
        const int cand = j >> 2, sub = j & 3;
        if (!((validw[buf][cand >> 5] >> (cand & 31)) & 1u)) return;
        const float4 c  = cbox[buf][cand];
        const float  ca = car[buf][cand];
        unsigned bits0 = 0, bits1 = 0;
        const int j0 = sub << 6;
        if (j0 + 31 > cand) {
            #pragma unroll
            for (int t = 0; t < 32; t++) {
                const int jj = j0 + t;
                if (jj > cand) {
                    float4 d = cbox[buf][jj];
                    if (iou_gt(c.x, c.y, c.z, c.w, ca,
                               d.x, d.y, d.z, d.w, car[buf][jj]))
                        bits0 |= (1u << t);
                }
            }
        }
        if (j0 + 63 > cand) {
            #pragma unroll
            for (int t = 0; t < 32; t++) {
                const int jj = j0 + 32 + t;
                if (jj > cand) {
                    float4 d = cbox[buf][jj];
                    if (iou_gt(c.x, c.y, c.z, c.w, ca,
                               d.x, d.y, d.z, d.w, car[buf][jj]))
                        bits1 |= (1u << t);
                }
            }
        }
        mat32[mb][cand][2 * sub]     = bits0;
        mat32[mb][cand][2 * sub + 1] = bits1;
    };

    // ---- prologue: stage(0); then A2(0) + stage(1) ----
    if (tid < CHUNK) stage(0, 0, tid);
    __syncthreads();
    if (tid < 768) {
        a2_job(tid, 0, 0);
        if (tid < CHUNK) a2_job(tid + 768, 0, 0);
    } else {
        stage(1, CHUNK, tid - 768);
    }
    __syncthreads();

    // ---- pipelined bitmap-chunked NMS ----
    for (int c = 0, r = 0; r < NBOX; c++, r += CHUNK) {
        const int cur = c % 3, nxt = (c + 1) % 3, nx2 = (c + 2) % 3;

        // A1: all threads, chunk c vs kept set, warp early-exit every 32 keeps
        {
            const int cand = tid >> 2, sub = tid & 3;
            const float4 cb = cbox[cur][cand];
            const float  ca = car[cur][cand];
            const int cnt = s_count;
            bool sup = false;
            int j = sub;
            for (int base = 0; base < cnt; base += 32) {
                const int jend = (cnt < base + 32) ? cnt : base + 32;
                for (; j < jend; j += SUBS) {
                    float4 kb = kbox[j];
                    sup |= iou_gt(cb.x, cb.y, cb.z, cb.w, ca,
                                  kb.x, kb.y, kb.z, kb.w, kar[j]);
                }
                if (base + 32 < cnt) {
                    unsigned bc = __ballot_sync(FULL, sup);
                    unsigned nib = bc | (bc >> 1) | (bc >> 2) | (bc >> 3);
                    if ((nib & 0x11111111u) == 0x11111111u) break;  // all 8 cands hit
                }
            }
            unsigned bal = __ballot_sync(FULL, sup);
            if (sub == 0)
                ssup[cand] = ((bal >> (lane & 28)) & 0xFu) ? 1 : 0;
        }
        __syncthreads();

        // B slot: resolve chunk c || A2(c+1) || stage(c+2)
        if (tid == 0) {
            const unsigned* ss32 = (const unsigned*)ssup;
            unsigned aw[NW];
            bool any_invalid = false;
            #pragma unroll
            for (int w = 0; w < NW; w++) {
                unsigned v = validw[cur][w];
                if (v != FULL) any_invalid = true;
                unsigned supb = 0;
                #pragma unroll
                for (int q = 0; q < 8; q++) {
                    unsigned x = ss32[w * 8 + q];
                    unsigned nib = (x & 1u) | ((x >> 7) & 2u)
                                 | ((x >> 14) & 4u) | ((x >> 21) & 8u);
                    supb |= nib << (q * 4);
                }
                aw[w] = v & ~supb;
            }

            int count = s_count;
            const int mb = c & 1;
            #pragma unroll
            for (int w = 0; w < NW; w++) {
                while (aw[w] && count < MAX_DET) {
                    const int bit = __ffs(aw[w]) - 1;
                    const int i = (w << 5) + bit;
                    aw[w] &= aw[w] - 1;
                    kbox[count] = cbox[cur][i];
                    kar[count]  = car[cur][i];
                    kidx[count] = cidx[cur][i];
                    count++;
                    const uint4 ra = *(const uint4*)&mat32[mb][i][0];
                    const uint4 rb = *(const uint4*)&mat32[mb][i][4];
                    aw[0] &= ~ra.x; aw[1] &= ~ra.y; aw[2] &= ~ra.z; aw[3] &= ~ra.w;
                    aw[4] &= ~rb.x; aw[5] &= ~rb.y; aw[6] &= ~rb.z; aw[7] &= ~rb.w;
                }
                if (count >= MAX_DET) break;
            }
            s_count = count;
            s_stop  = (count >= MAX_DET) || any_invalid;
        } else {
            if (r + CHUNK < NBOX) {
                const int j = tid - 32;
                if (j >= 0) {
                    a2_job(j, nxt, (c + 1) & 1);
                    if (j < 32) a2_job(j + 992, nxt, (c + 1) & 1);
                }
            }
            if (tid >= 768 && r + 2 * CHUNK < NBOX)
                stage(nx2, r + 2 * CHUNK, tid - 768);
        }
        __syncthreads();
        if (s_stop) break;
    }

    const int count = s_count;

    // ---- outputs (zero-pad beyond count), vectorized ----
    float4* ob4 = (float4*)(nms_box + (size_t)b * MAX_DET * 4);
    for (int t = tid; t < MAX_DET; t += THREADS)
        ob4[t] = (t < count) ? bb4[kidx[t]] : make_float4(0.f, 0.f, 0.f, 0.f);

    float4* oc4 = (float4*)(nms_cls + (size_t)b * MAX_DET * NCLS);
    const float4* cs4 = (const float4*)cls_soft;
    for (int t = tid; t < MAX_DET * (NCLS / 4); t += THREADS) {
        int k = t / (NCLS / 4), c = t % (NCLS / 4);
        oc4[t] = (k < count)
               ? cs4[((size_t)b * NBOX + (size_t)kidx[k]) * (NCLS / 4) + c]
               : make_float4(0.f, 0.f, 0.f, 0.f);
    }
}

// ---------------------------------------------------------------------------
extern "C" void kernel_launch(void* const* d_in, const int* in_sizes, int n_in,
                              void* d_out, int out_size)
{
    const float* boxes;
    const float* cls;
    if (in_sizes[0] == BATCH * NBOX * 4) {
        boxes = (const float*)d_in[0];
        cls   = (const float*)d_in[1];
    } else {
        boxes = (const float*)d_in[1];
        cls   = (const float*)d_in[0];
    }

    float* out      = (float*)d_out;
    float* nms_box  = out;                                  // [16,100,4]
    float* nms_cls  = out + BATCH * MAX_DET * 4;            // [16,100,80]
    float* cls_pred = out + BATCH * MAX_DET * 4
                          + BATCH * MAX_DET * NCLS;         // [16,4096,80]

    unsigned long long* keys = nullptr;
    cudaGetSymbolAddress((void**)&keys, g_keys);

    const int DYN_SMEM = NBOX * (int)sizeof(float4)
                       + NBOX * (int)sizeof(unsigned long long)
                       + NBOX * (int)sizeof(float);         // 112 KB
    static int smem_set = 0;
    if (!smem_set) {
        cudaFuncSetAttribute(nms_kernel,
                             cudaFuncAttributeMaxDynamicSharedMemorySize,
                             DYN_SMEM);
        smem_set = 1;
    }

    const int rows = BATCH * NBOX;
    softmax_key_kernel<<<rows / 8, 256>>>(cls, cls_pred, keys);
    presort_kernel<<<BATCH * 4, 512>>>(keys);
    merge2048_kernel<<<BATCH * 2, 512>>>(keys);
    nms_kernel<<<BATCH, THREADS, DYN_SMEM>>>(boxes, cls_pred, keys, nms_box, nms_cls);
}

// round 16
// speedup vs baseline: 1.2204x; 1.2204x over previous
#include <cuda_runtime.h>
#include <stdint.h>

#define BATCH    16
#define NBOX     4096
#define NCLS     80
#define MAX_DET  100
#define IOU_THR  0.5f
#define CONF_THR 0.5f
#define FULL     0xffffffffu
#define CHUNK    256
#define SUBS     4                  // 1024 threads / 256 candidates
#define NW       (CHUNK / 32)       // 8 mask words
#define THREADS  1024

// scratch: per-row sort keys  (score_bits << 32) | (0xFFFFFFFF - idx)
__device__ unsigned long long g_keys[BATCH * NBOX];

// guarded IoU>0.5 test. Fast path: IoU>0.5 <=> 3*inter > aa+ab.
// g>0 implies inter>0 (areas >= 0). Borderline band falls back to the exact
// divide with uni = fl(fl(aa+ab) - inter), identical rounding to reference.
__device__ __forceinline__ bool iou_gt(float y1a, float x1a, float y2a, float x2a, float aa,
                                       float y1b, float x1b, float y2b, float x2b, float ab)
{
    float ih = fmaxf(0.0f, fminf(y2a, y2b) - fmaxf(y1a, y1b));
    float iw = fmaxf(0.0f, fminf(x2a, x2b) - fmaxf(x1a, x1b));
    float inter = ih * iw;
    float t   = aa + ab;
    float uni = t - inter;
    float g   = fmaf(3.0f, inter, -t);           // = 2*(inter - 0.5*uni)
    if (fabsf(g) <= uni * 1e-5f) {               // borderline: exact semantics
        float iou = (inter > 0.0f) ? inter / uni : 0.0f;
        return iou > IOU_THR;
    }
    return g > 0.0f;
}

__device__ __forceinline__ void ce64(unsigned long long& a, unsigned long long& b, bool desc)
{
    bool sw = desc ? (a < b) : (a > b);
    if (sw) { unsigned long long t = a; a = b; b = t; }
}

__device__ __forceinline__ unsigned long long shfl_step(unsigned long long v, int j,
                                                        bool desc, int lane)
{
    unsigned long long w = __shfl_xor_sync(FULL, v, j);
    bool upper   = (lane & j) != 0;
    bool takeMax = desc ^ upper;
    return takeMax ? (v > w ? v : w) : (v < w ? v : w);
}

// ---------------------------------------------------------------------------
// Kernel 1: softmax(square(x*10)) per row, write cls_predictions, emit keys.
// ---------------------------------------------------------------------------
__global__ void __launch_bounds__(256)
softmax_key_kernel(const float* __restrict__ cls_in,
                   float* __restrict__ cls_out,
                   unsigned long long* __restrict__ keys)
{
    const int lane = threadIdx.x & 31;
    const int row  = blockIdx.x * (blockDim.x >> 5) + (threadIdx.x >> 5);
    if (row >= BATCH * NBOX) return;

    const float* in = cls_in + (size_t)row * NCLS;

    const bool has2 = lane < (NCLS - 64);
    float x0 = in[lane]      * 10.0f;
    float x1 = in[lane + 32] * 10.0f;
    float x2 = has2 ? in[lane + 64] * 10.0f : 0.0f;
    float a0 = x0 * x0, a1 = x1 * x1, a2 = x2 * x2;

    float amax = fmaxf(a0, a1);
    if (has2) amax = fmaxf(amax, a2);
    amax = __uint_as_float(__reduce_max_sync(FULL, __float_as_uint(amax)));

    float e0 = expf(a0 - amax);
    float e1 = expf(a1 - amax);
    float e2 = has2 ? expf(a2 - amax) : 0.0f;

    float s = e0 + e1 + e2;
    #pragma unroll
    for (int o = 16; o; o >>= 1)
        s += __shfl_xor_sync(FULL, s, o);

    const float recip = 1.0f / s;

    float* out = cls_out + (size_t)row * NCLS;
    out[lane]      = e0 * recip;
    out[lane + 32] = e1 * recip;
    if (has2) out[lane + 64] = e2 * recip;

    if (lane == 0) {
        const unsigned n = (unsigned)(row & (NBOX - 1));
        keys[row] = ((unsigned long long)__float_as_uint(recip) << 32)
                  | (unsigned long long)(0xffffffffu - n);
    }
}

// ---------------------------------------------------------------------------
// Kernel 1.5a: presort — sort each 1024-run (global stages k=2..1024).
// ---------------------------------------------------------------------------
__global__ void __launch_bounds__(512)
presort_kernel(unsigned long long* __restrict__ keys)
{
    __shared__ unsigned long long s[1024];
    const int tid  = threadIdx.x;
    const int lane = tid & 31;
    const bool desc_run = ((blockIdx.x & 1) == 0);
    unsigned long long* kg = keys + (size_t)blockIdx.x * 1024;

    s[tid]       = kg[tid];
    s[tid + 512] = kg[tid + 512];
    __syncthreads();

    {
        const int i0 = tid, i1 = tid + 512;
        unsigned long long v0 = s[i0], v1 = s[i1];
        #pragma unroll
        for (int k = 2; k <= 32; k <<= 1) {
            const bool d0 = ((i0 & k) == 0);
            #pragma unroll
            for (int j = k >> 1; j >= 1; j >>= 1) {
                v0 = shfl_step(v0, j, d0, lane);
                v1 = shfl_step(v1, j, d0, lane);
            }
        }
        s[i0] = v0; s[i1] = v1;
    }
    __syncthreads();

    for (int k = 64; k <= 1024; k <<= 1) {
        for (int j = k >> 1; j >= 32; j >>= 1) {
            const int p = tid;
            const int i = ((p & ~(j - 1)) << 1) | (p & (j - 1));
            const int l = i | j;
            const bool d = (k == 1024) ? desc_run : ((i & k) == 0);
            unsigned long long a = s[i], c = s[l];
            bool sw = d ? (a < c) : (a > c);
            if (sw) { s[i] = c; s[l] = a; }
            __syncthreads();
        }
        {
            const int i0 = tid, i1 = tid + 512;
            unsigned long long v0 = s[i0], v1 = s[i1];
            const bool d0 = (k == 1024) ? desc_run : ((i0 & k) == 0);
            const bool d1 = (k == 1024) ? desc_run : ((i1 & k) == 0);
            #pragma unroll
            for (int j = 16; j >= 1; j >>= 1) {
                v0 = shfl_step(v0, j, d0, lane);
                v1 = shfl_step(v1, j, d1, lane);
            }
            s[i0] = v0; s[i1] = v1;
        }
        __syncthreads();
    }

    kg[tid]       = s[tid];
    kg[tid + 512] = s[tid + 512];
}

// ---------------------------------------------------------------------------
// Kernel 1.5b: merge2048 — global bitonic stage k=2048 only.
// ---------------------------------------------------------------------------
__global__ void __launch_bounds__(512)
merge2048_kernel(unsigned long long* __restrict__ keys)
{
    __shared__ unsigned long long s[2048];
    const int tid  = threadIdx.x;
    const int lane = tid & 31;
    const int warp = tid >> 5;
    const bool d = ((blockIdx.x & 1) == 0);
    unsigned long long* kg = keys + (size_t)blockIdx.x * 2048;

    #pragma unroll
    for (int m = 0; m < 4; m++) s[tid + m * 512] = kg[tid + m * 512];
    __syncthreads();

    for (int j = 1024; j >= 128; j >>= 1) {
        #pragma unroll
        for (int q = 0; q < 2; q++) {
            const int p = tid + q * 512;
            const int i = ((p & ~(j - 1)) << 1) | (p & (j - 1));
            const int l = i | j;
            unsigned long long a = s[i], c = s[l];
            bool sw = d ? (a < c) : (a > c);
            if (sw) { s[i] = c; s[l] = a; }
        }
        __syncthreads();
    }

    const int base = warp << 7;
    unsigned long long r0 = s[base + lane];
    unsigned long long r1 = s[base + 32 + lane];
    unsigned long long r2 = s[base + 64 + lane];
    unsigned long long r3 = s[base + 96 + lane];
    ce64(r0, r2, d); ce64(r1, r3, d);
    ce64(r0, r1, d); ce64(r2, r3, d);
    #pragma unroll
    for (int j = 16; j >= 1; j >>= 1) {
        r0 = shfl_step(r0, j, d, lane);
        r1 = shfl_step(r1, j, d, lane);
        r2 = shfl_step(r2, j, d, lane);
        r3 = shfl_step(r3, j, d, lane);
    }
    kg[base + lane]      = r0;
    kg[base + 32 + lane] = r1;
    kg[base + 64 + lane] = r2;
    kg[base + 96 + lane] = r3;
}

// ---------------------------------------------------------------------------
// Kernel 2: finish sort (k=4096 only, uniformly descending) + bitmap NMS.
// (R14-verified structure: gated A2 in A-slot; B + next-chunk staging share
//  the B-slot; double-buffered chunks.)
// Dynamic smem: float4 sbox[NBOX] | u64 sk[NBOX] | float sarea[NBOX]  (112KB)
// ---------------------------------------------------------------------------
__global__ void __launch_bounds__(THREADS, 1)
nms_kernel(const float* __restrict__ boxes,        // [B,N,4]
           const float* __restrict__ cls_soft,     // [B,N,C]
           const unsigned long long* __restrict__ keys,
           float* __restrict__ nms_box,            // [B,MAX_DET,4]
           float* __restrict__ nms_cls)            // [B,MAX_DET,C]
{
    extern __shared__ char dyn[];
    float4*             sbox  = (float4*)dyn;                       // 64KB
    unsigned long long* sk    = (unsigned long long*)(sbox + NBOX); // 32KB
    float*              sarea = (float*)(sk + NBOX);                // 16KB

    __shared__ float4        kbox[MAX_DET];       // kept set
    __shared__ float         kar[MAX_DET];
    __shared__ int           kidx[MAX_DET];
    __shared__ float4        cbox[2][CHUNK];      // double-buffered chunk
    __shared__ float         car[2][CHUNK];
    __shared__ int           cidx[2][CHUNK];
    __shared__ unsigned      validw[2][NW];
    __shared__ unsigned char ssup[CHUNK];
    __shared__ __align__(16) unsigned mat32[CHUNK][NW];   // 8KB matrix
    __shared__ int s_count, s_stop;

    const int b    = blockIdx.x;
    const int tid  = threadIdx.x;
    const int lane = tid & 31;
    const int warp = tid >> 5;

    // ---- load keys (pre-sorted 2048-runs) + pre-normalized boxes ----
    const float4* bb4 = (const float4*)(boxes + (size_t)b * NBOX * 4);
    #pragma unroll
    for (int s = 0; s < NBOX / THREADS; s++) {
        const int i = tid + s * THREADS;
        sk[i] = keys[b * NBOX + i];
        float4 r = bb4[i];
        float y1 = fminf(r.x, r.z), y2 = fmaxf(r.x, r.z);
        float x1 = fminf(r.y, r.w), x2 = fmaxf(r.y, r.w);
        sbox[i]  = make_float4(y1, x1, y2, x2);
        sarea[i] = (y2 - y1) * (x2 - x1);
    }
    if (tid == 0) { s_count = 0; s_stop = 0; }
    __syncthreads();

    // ---- bitonic stage k=4096 (all descending): smem j=2048..128 ----
    for (int j = 2048; j >= 128; j >>= 1) {
        #pragma unroll
        for (int q = 0; q < NBOX / 2 / THREADS; q++) {
            const int p = tid + q * THREADS;
            const int i = ((p & ~(j - 1)) << 1) | (p & (j - 1));
            const int l = i | j;
            unsigned long long a = sk[i], c = sk[l];
            if (a < c) { sk[i] = c; sk[l] = a; }
        }
        __syncthreads();
    }
    {   // register mega-pass per 128-tile: j = 64, 32, <=16 (desc)
        const int base = warp << 7;
        unsigned long long r0 = sk[base + lane];
        unsigned long long r1 = sk[base + 32 + lane];
        unsigned long long r2 = sk[base + 64 + lane];
        unsigned long long r3 = sk[base + 96 + lane];
        ce64(r0, r2, true); ce64(r1, r3, true);
        ce64(r0, r1, true); ce64(r2, r3, true);
        #pragma unroll
        for (int j = 16; j >= 1; j >>= 1) {
            r0 = shfl_step(r0, j, true, lane);
            r1 = shfl_step(r1, j, true, lane);
            r2 = shfl_step(r2, j, true, lane);
            r3 = shfl_step(r3, j, true, lane);
        }
        sk[base + lane]      = r0;
        sk[base + 32 + lane] = r1;
        sk[base + 64 + lane] = r2;
        sk[base + 96 + lane] = r3;
    }
    __syncthreads();

    // ---- prologue: stage chunk 0 into buffer 0 ----
    if (tid < CHUNK) {
        const unsigned long long key = sk[tid];
        const float score = __uint_as_float((unsigned)(key >> 32));
        const int   idx = (int)(0xffffffffu - (unsigned)(key & 0xffffffffu));
        cidx[0][tid] = idx;
        cbox[0][tid] = sbox[idx];
        car[0][tid]  = sarea[idx];
        unsigned vb = __ballot_sync(FULL, score > CONF_THR);
        if (lane == 0) validw[0][warp] = vb;
    }
    __syncthreads();

    // ---- double-buffered bitmap-chunked NMS ----
    int cur = 0;
    for (int r = 0; r < NBOX; r += CHUNK) {
        // Phase A: all threads; A1 with warp early-exit, then gated A2
        {
            const int cand = tid >> 2, sub = tid & 3;
            const float4 c  = cbox[cur][cand];
            const float  ca = car[cur][cand];
            const bool vcand = (validw[cur][cand >> 5] >> (cand & 31)) & 1u;

            // A1: candidate vs kept set; every 32 keeps, warp early-exit if
            // all 8 candidates of this warp already have a hit (OR-exact).
            const int cnt = s_count;
            bool sup = false;
            int j = sub;
            for (int base = 0; base < cnt; base += 32) {
                const int jend = (cnt < base + 32) ? cnt : base + 32;
                for (; j < jend; j += SUBS) {
                    float4 kb = kbox[j];
                    sup |= iou_gt(c.x, c.y, c.z, c.w, ca,
                                  kb.x, kb.y, kb.z, kb.w, kar[j]);
                }
                if (base + 32 < cnt) {
                    unsigned bc = __ballot_sync(FULL, sup);
                    unsigned nib = bc | (bc >> 1) | (bc >> 2) | (bc >> 3);
                    if ((nib & 0x11111111u) == 0x11111111u) break;
                }
            }
            unsigned bal = __ballot_sync(FULL, sup);
            if (sub == 0)
                ssup[cand] = ((bal >> (lane & 28)) & 0xFu) ? 1 : 0;

            const bool alive = vcand && (((bal >> (lane & 28)) & 0xFu) == 0u);

            // A2: matrix row words (64 bits per sub) only for alive rows
            if (alive) {
                unsigned bits0 = 0, bits1 = 0;
                const int j0 = sub << 6;
                if (j0 + 31 > cand) {
                    #pragma unroll
                    for (int t = 0; t < 32; t++) {
                        const int jj = j0 + t;
                        if (jj > cand) {
                            float4 d = cbox[cur][jj];
                            if (iou_gt(c.x, c.y, c.z, c.w, ca,
                                       d.x, d.y, d.z, d.w, car[cur][jj]))
                                bits0 |= (1u << t);
                        }
                    }
                }
                if (j0 + 63 > cand) {
                    #pragma unroll
                    for (int t = 0; t < 32; t++) {
                        const int jj = j0 + 32 + t;
                        if (jj > cand) {
                            float4 d = cbox[cur][jj];
                            if (iou_gt(c.x, c.y, c.z, c.w, ca,
                                       d.x, d.y, d.z, d.w, car[cur][jj]))
                                bits1 |= (1u << t);
                        }
                    }
                }
                mat32[cand][2 * sub]     = bits0;
                mat32[cand][2 * sub + 1] = bits1;
            }
        }
        __syncthreads();

        // Phase B (thread 0) + stage next chunk (warps 16-23) concurrently
        if (tid == 0) {
            const unsigned* ss32 = (const unsigned*)ssup;
            unsigned aw[NW];
            bool any_invalid = false;
            #pragma unroll
            for (int w = 0; w < NW; w++) {
                unsigned v = validw[cur][w];
                if (v != FULL) any_invalid = true;
                unsigned supb = 0;
                #pragma unroll
                for (int q = 0; q < 8; q++) {          // 4 bytes -> 4 bits
                    unsigned x = ss32[w * 8 + q];
                    unsigned nib = (x & 1u) | ((x >> 7) & 2u)
                                 | ((x >> 14) & 4u) | ((x >> 21) & 8u);
                    supb |= nib << (q * 4);
                }
                aw[w] = v & ~supb;
            }

            int count = s_count;
            #pragma unroll
            for (int w = 0; w < NW; w++) {
                while (aw[w] && count < MAX_DET) {
                    const int bit = __ffs(aw[w]) - 1;
                    const int i = (w << 5) + bit;
                    aw[w] &= aw[w] - 1;
                    kbox[count] = cbox[cur][i];
                    kar[count]  = car[cur][i];
                    kidx[count] = cidx[cur][i];
                    count++;
                    const uint4 ra = *(const uint4*)&mat32[i][0];
                    const uint4 rb = *(const uint4*)&mat32[i][4];
                    aw[0] &= ~ra.x; aw[1] &= ~ra.y; aw[2] &= ~ra.z; aw[3] &= ~ra.w;
                    aw[4] &= ~rb.x; aw[5] &= ~rb.y; aw[6] &= ~rb.z; aw[7] &= ~rb.w;
                }
                if (count >= MAX_DET) break;
            }
            s_count = count;
            s_stop  = (count >= MAX_DET) || any_invalid;
        } else if (tid >= 512 && tid < 512 + CHUNK && (r + CHUNK) < NBOX) {
            const int c = tid - 512;
            const int nxt = cur ^ 1;
            const unsigned long long key = sk[r + CHUNK + c];
            const float score = __uint_as_float((unsigned)(key >> 32));
            const int   idx = (int)(0xffffffffu - (unsigned)(key & 0xffffffffu));
            cidx[nxt][c] = idx;
            cbox[nxt][c] = sbox[idx];
            car[nxt][c]  = sarea[idx];
            unsigned vb = __ballot_sync(FULL, score > CONF_THR);
            if (lane == 0) validw[nxt][c >> 5] = vb;
        }
        __syncthreads();
        if (s_stop) break;
        cur ^= 1;
    }

    const int count = s_count;

    // ---- outputs (zero-pad beyond count), vectorized ----
    float4* ob4 = (float4*)(nms_box + (size_t)b * MAX_DET * 4);
    for (int t = tid; t < MAX_DET; t += THREADS)
        ob4[t] = (t < count) ? bb4[kidx[t]] : make_float4(0.f, 0.f, 0.f, 0.f);

    float4* oc4 = (float4*)(nms_cls + (size_t)b * MAX_DET * NCLS);
    const float4* cs4 = (const float4*)cls_soft;
    for (int t = tid; t < MAX_DET * (NCLS / 4); t += THREADS) {
        int k = t / (NCLS / 4), c = t % (NCLS / 4);
        oc4[t] = (k < count)
               ? cs4[((size_t)b * NBOX + (size_t)kidx[k]) * (NCLS / 4) + c]
               : make_float4(0.f, 0.f, 0.f, 0.f);
    }
}

// ---------------------------------------------------------------------------
extern "C" void kernel_launch(void* const* d_in, const int* in_sizes, int n_in,
                              void* d_out, int out_size)
{
    const float* boxes;
    const float* cls;
    if (in_sizes[0] == BATCH * NBOX * 4) {
        boxes = (const float*)d_in[0];
        cls   = (const float*)d_in[1];
    } else {
        boxes = (const float*)d_in[1];
        cls   = (const float*)d_in[0];
    }

    float* out      = (float*)d_out;
    float* nms_box  = out;                                  // [16,100,4]
    float* nms_cls  = out + BATCH * MAX_DET * 4;            // [16,100,80]
    float* cls_pred = out + BATCH * MAX_DET * 4
                          + BATCH * MAX_DET * NCLS;         // [16,4096,80]

    unsigned long long* keys = nullptr;
    cudaGetSymbolAddress((void**)&keys, g_keys);

    const int DYN_SMEM = NBOX * (int)sizeof(float4)
                       + NBOX * (int)sizeof(unsigned long long)
                       + NBOX * (int)sizeof(float);         // 112 KB
    static int smem_set = 0;
    if (!smem_set) {
        cudaFuncSetAttribute(nms_kernel,
                             cudaFuncAttributeMaxDynamicSharedMemorySize,
                             DYN_SMEM);
        smem_set = 1;
    }

    const int rows = BATCH * NBOX;
    softmax_key_kernel<<<rows / 8, 256>>>(cls, cls_pred, keys);
    presort_kernel<<<BATCH * 4, 512>>>(keys);
    merge2048_kernel<<<BATCH * 2, 512>>>(keys);
    nms_kernel<<<BATCH, THREADS, DYN_SMEM>>>(boxes, cls_pred, keys, nms_box, nms_cls);
}